// round 1
// baseline (speedup 1.0000x reference)
#include <cuda_runtime.h>
#include <math.h>

#define BB 2
#define LL 2048
#define DD 1024
#define HH 16
#define DK 64
#define BL (BB*LL)              // 4096

// ---------------- scratch (device globals: no allocation allowed) ----------
__device__ float g_Q[BL * DD];                 // 16 MB
__device__ float g_K[BL * DD];                 // 16 MB
__device__ float g_V[BL * DD];                 // 16 MB
__device__ float g_S[(size_t)BB * HH * LL * LL]; // 512 MB scores/probs
__device__ float g_ctx[BL * DD];               // 16 MB

// ---------------- generic 64x64 fp32 GEMM tile (NN) -------------------------
// C[m0:m0+64, n0:n0+64] = A[M,K](lda) @ B[K,N](ldb) (+bias, optional row scale on A)
__device__ __forceinline__ void sgemm_tile64(
    const float* __restrict__ A, int lda,
    const float* __restrict__ B, int ldb,
    float* __restrict__ C, int ldc,
    int K, int m0, int n0,
    const float* __restrict__ bias,
    const float* __restrict__ rowscale)
{
    __shared__ float As[16][64];   // [k][m]
    __shared__ float Bs[16][64];   // [k][n]
    int tid = threadIdx.x;
    int tx = tid & 15, ty = tid >> 4;
    int a_row = tid >> 2, a_c4 = (tid & 3) << 2;   // A: 64 rows x 16 k per tile
    int b_row = tid >> 4, b_c4 = (tid & 15) << 2;  // B: 16 k x 64 n

    float rs = rowscale ? rowscale[m0 + a_row] : 1.0f;

    float acc[4][4];
#pragma unroll
    for (int i = 0; i < 4; i++)
#pragma unroll
        for (int j = 0; j < 4; j++) acc[i][j] = 0.0f;

    const float* Aptr = A + (size_t)(m0 + a_row) * lda + a_c4;
    const float* Bptr = B + (size_t)b_row * ldb + n0 + b_c4;

    for (int k0 = 0; k0 < K; k0 += 16) {
        float4 av = *(const float4*)(Aptr + k0);
        float4 bv = *(const float4*)(Bptr + (size_t)k0 * ldb);
        __syncthreads();
        As[a_c4 + 0][a_row] = av.x * rs;
        As[a_c4 + 1][a_row] = av.y * rs;
        As[a_c4 + 2][a_row] = av.z * rs;
        As[a_c4 + 3][a_row] = av.w * rs;
        *(float4*)&Bs[b_row][b_c4] = bv;
        __syncthreads();
#pragma unroll
        for (int kk = 0; kk < 16; kk++) {
            float a[4], b[4];
#pragma unroll
            for (int i = 0; i < 4; i++) a[i] = As[kk][(ty << 2) + i];
#pragma unroll
            for (int j = 0; j < 4; j++) b[j] = Bs[kk][(tx << 2) + j];
#pragma unroll
            for (int i = 0; i < 4; i++)
#pragma unroll
                for (int j = 0; j < 4; j++) acc[i][j] += a[i] * b[j];
        }
    }

#pragma unroll
    for (int i = 0; i < 4; i++) {
        int m = m0 + (ty << 2) + i;
#pragma unroll
        for (int j = 0; j < 4; j++) {
            int n = n0 + (tx << 2) + j;
            float v = acc[i][j];
            if (bias) v += bias[n];
            C[(size_t)m * ldc + n] = v;
        }
    }
}

// projection / output GEMM wrapper: grid (N/64, M/64)
__global__ void __launch_bounds__(256) proj_gemm(
    const float* __restrict__ A, int lda,
    const float* __restrict__ B, int ldb,
    float* __restrict__ C, int ldc, int K,
    const float* __restrict__ bias,
    const float* __restrict__ rowscale)
{
    sgemm_tile64(A, lda, B, ldb, C, ldc, K,
                 blockIdx.y << 6, blockIdx.x << 6, bias, rowscale);
}

// context GEMM: per (b,h): ctx[b,:,h*64:(h+1)*64] = P[b,h] @ V[b,h]
// grid (L/64 m-tiles, B*H)
__global__ void __launch_bounds__(256) context_gemm(
    const float* __restrict__ S, const float* __restrict__ V, float* __restrict__ ctx)
{
    int z = blockIdx.y;
    int b = z >> 4, h = z & 15;
    const float* A = S + (size_t)z * LL * LL;
    const float* Bv = V + (size_t)b * LL * DD + (size_t)h * DK;
    float* C = ctx + (size_t)b * LL * DD + (size_t)h * DK;
    sgemm_tile64(A, LL, Bv, DD, C, DD, LL, blockIdx.x << 6, 0, nullptr, nullptr);
}

// ---------------- scores: S = Q Kt / 8 - 0.1*|q-k| + log(delta_k + 1e-6) -----
// grid (L/64 n-tiles, L/64 m-tiles, B*H)
__global__ void __launch_bounds__(256) scores_kernel(
    const float* __restrict__ Q, const float* __restrict__ Kb,
    const float* __restrict__ delta, float* __restrict__ S)
{
    __shared__ float Qs[64][65];   // [d][m]
    __shared__ float Ks[64][65];   // [d][n]
    __shared__ float relb[64];

    int z = blockIdx.z, b = z >> 4, h = z & 15;
    int m0 = blockIdx.y << 6, n0 = blockIdx.x << 6;
    const float* Aq = Q + (size_t)b * LL * DD + (size_t)h * DK;
    const float* Ak = Kb + (size_t)b * LL * DD + (size_t)h * DK;

    int tid = threadIdx.x;
    int r = tid >> 2, c0 = (tid & 3) << 2;
#pragma unroll
    for (int jj = 0; jj < 4; jj++) {
        int c = c0 + (jj << 4);
        float4 qv = *(const float4*)(Aq + (size_t)(m0 + r) * DD + c);
        float4 kv = *(const float4*)(Ak + (size_t)(n0 + r) * DD + c);
        Qs[c + 0][r] = qv.x; Qs[c + 1][r] = qv.y; Qs[c + 2][r] = qv.z; Qs[c + 3][r] = qv.w;
        Ks[c + 0][r] = kv.x; Ks[c + 1][r] = kv.y; Ks[c + 2][r] = kv.z; Ks[c + 3][r] = kv.w;
    }
    if (tid < 64) relb[tid] = logf(delta[(size_t)b * LL + n0 + tid] + 1e-6f);
    __syncthreads();

    int tx = tid & 15, ty = tid >> 4;
    float acc[4][4];
#pragma unroll
    for (int i = 0; i < 4; i++)
#pragma unroll
        for (int j = 0; j < 4; j++) acc[i][j] = 0.0f;

#pragma unroll
    for (int d = 0; d < 64; d++) {
        float a[4], bb[4];
#pragma unroll
        for (int i = 0; i < 4; i++) a[i] = Qs[d][(ty << 2) + i];
#pragma unroll
        for (int j = 0; j < 4; j++) bb[j] = Ks[d][(tx << 2) + j];
#pragma unroll
        for (int i = 0; i < 4; i++)
#pragma unroll
            for (int j = 0; j < 4; j++) acc[i][j] += a[i] * bb[j];
    }

#pragma unroll
    for (int i = 0; i < 4; i++) {
        int m = m0 + (ty << 2) + i;
        float4 o;
        float* op = (float*)&o;
#pragma unroll
        for (int j = 0; j < 4; j++) {
            int n = n0 + (tx << 2) + j;
            op[j] = acc[i][j] * 0.125f - 0.1f * fabsf((float)(m - n)) + relb[(tx << 2) + j];
        }
        *(float4*)(S + ((size_t)z * LL + m) * LL + n0 + (tx << 2)) = o;
    }
}

// ---------------- row softmax over S (in place) ------------------------------
// grid = B*H*L blocks, 256 threads, 8 elements / thread
__global__ void __launch_bounds__(256) softmax_kernel(float* __restrict__ S)
{
    float* p = S + (size_t)blockIdx.x * LL;
    int tid = threadIdx.x;
    float r[8];
#pragma unroll
    for (int j = 0; j < 8; j++) r[j] = p[tid + (j << 8)];

    float m = r[0];
#pragma unroll
    for (int j = 1; j < 8; j++) m = fmaxf(m, r[j]);
#pragma unroll
    for (int off = 16; off; off >>= 1) m = fmaxf(m, __shfl_xor_sync(0xffffffffu, m, off));

    __shared__ float redm[8];
    __shared__ float reds[8];
    int wid = tid >> 5, lid = tid & 31;
    if (lid == 0) redm[wid] = m;
    __syncthreads();
    m = redm[0];
#pragma unroll
    for (int w = 1; w < 8; w++) m = fmaxf(m, redm[w]);

    float s = 0.0f;
#pragma unroll
    for (int j = 0; j < 8; j++) { r[j] = __expf(r[j] - m); s += r[j]; }
#pragma unroll
    for (int off = 16; off; off >>= 1) s += __shfl_xor_sync(0xffffffffu, s, off);
    if (lid == 0) reds[wid] = s;
    __syncthreads();
    s = 0.0f;
#pragma unroll
    for (int w = 0; w < 8; w++) s += reds[w];

    float inv = 1.0f / s;
#pragma unroll
    for (int j = 0; j < 8; j++) p[tid + (j << 8)] = r[j] * inv;
}

// ---------------- mean over heads -> d_out[4194304 ...] ---------------------
// grid = B*L blocks
__global__ void __launch_bounds__(256) mean_kernel(
    const float* __restrict__ S, float* __restrict__ outm)
{
    int bq = blockIdx.x;            // b*L + q
    int b = bq >> 11, q = bq & 2047;
    int tid = threadIdx.x;
    float acc[8];
#pragma unroll
    for (int j = 0; j < 8; j++) acc[j] = 0.0f;
    for (int h = 0; h < HH; h++) {
        const float* p = S + (((size_t)(b * HH + h) * LL + q) << 11);
#pragma unroll
        for (int j = 0; j < 8; j++) acc[j] += p[tid + (j << 8)];
    }
    float* o = outm + ((size_t)bq << 11);
#pragma unroll
    for (int j = 0; j < 8; j++) o[tid + (j << 8)] = acc[j] * (1.0f / 16.0f);
}

// ---------------- launch ------------------------------------------------------
extern "C" void kernel_launch(void* const* d_in, const int* in_sizes, int n_in,
                              void* d_out, int out_size)
{
    const float* x   = (const float*)d_in[0];
    const float* dr  = (const float*)d_in[1];
    const float* Wq  = (const float*)d_in[2];
    const float* bq  = (const float*)d_in[3];
    const float* Wk  = (const float*)d_in[4];
    const float* bk  = (const float*)d_in[5];
    const float* Wv  = (const float*)d_in[6];
    const float* bv  = (const float*)d_in[7];
    const float* Wo  = (const float*)d_in[8];
    const float* bo  = (const float*)d_in[9];
    float* out = (float*)d_out;

    float *pQ, *pK, *pV, *pS, *pC;
    cudaGetSymbolAddress((void**)&pQ, g_Q);
    cudaGetSymbolAddress((void**)&pK, g_K);
    cudaGetSymbolAddress((void**)&pV, g_V);
    cudaGetSymbolAddress((void**)&pS, g_S);
    cudaGetSymbolAddress((void**)&pC, g_ctx);

    dim3 gproj(DD / 64, BL / 64);          // (16, 64)
    proj_gemm<<<gproj, 256>>>(x, DD, Wq, DD, pQ, DD, DD, bq, nullptr);
    proj_gemm<<<gproj, 256>>>(x, DD, Wk, DD, pK, DD, DD, bk, nullptr);
    proj_gemm<<<gproj, 256>>>(x, DD, Wv, DD, pV, DD, DD, bv, dr);

    dim3 gsc(LL / 64, LL / 64, BB * HH);   // (32, 32, 32)
    scores_kernel<<<gsc, 256>>>(pQ, pK, dr, pS);

    softmax_kernel<<<BB * HH * LL, 256>>>(pS);

    if (out_size >= (BL * DD + BB * LL * LL)) {
        mean_kernel<<<BB * LL, 256>>>(pS, out + (size_t)BL * DD);
    }

    dim3 gctx(LL / 64, BB * HH);           // (32, 32)
    context_gemm<<<gctx, 256>>>(pS, pV, pC);

    proj_gemm<<<gproj, 256>>>(pC, DD, Wo, DD, out, DD, DD, bo, nullptr);
}

// round 3
// speedup vs baseline: 1.5464x; 1.5464x over previous
#include <cuda_runtime.h>
#include <math.h>

#define BB 2
#define LL 2048
#define DD 1024
#define HH 16
#define DK 64
#define BL (BB*LL)              // 4096

// ---------------- scratch (device globals: no allocation allowed) ----------
__device__ float g_Q[BL * DD];
__device__ float g_K[BL * DD];
__device__ float g_V[BL * DD];
__device__ float g_ctx[BL * DD];
__device__ float g_S[(size_t)BB * HH * LL * LL];   // 512 MB raw scores -> probs

typedef unsigned long long u64;

__device__ __forceinline__ u64 pack2(float lo, float hi) {
    u64 r; asm("mov.b64 %0, {%1, %2};" : "=l"(r) : "f"(lo), "f"(hi)); return r;
}
__device__ __forceinline__ float2 unpack2(u64 v) {
    float2 r; asm("mov.b64 {%0, %1}, %2;" : "=f"(r.x), "=f"(r.y) : "l"(v)); return r;
}
#define FFMA2(c, a, b) asm("fma.rn.f32x2 %0, %1, %2, %0;" : "+l"(c) : "l"(a), "l"(b))

// fast exp: 2^t split, degree-6 poly on [-0.5,0.5], rel err ~1e-7
__device__ __forceinline__ float fexp(float x) {
    x = fmaxf(x, -87.0f);
    float t = x * 1.4426950408889634f;
    int   ei = __float2int_rn(t);
    float f  = t - (float)ei;
    float p = 1.5403530e-4f;
    p = fmaf(p, f, 1.3333558e-3f);
    p = fmaf(p, f, 9.6181291e-3f);
    p = fmaf(p, f, 5.5504109e-2f);
    p = fmaf(p, f, 2.4022651e-1f);
    p = fmaf(p, f, 6.9314718e-1f);
    p = fmaf(p, f, 1.0f);
    return p * __int_as_float((ei + 127) << 23);
}

// 8x8 micro-tile FFMA2 core over a 16-deep k-slab in smem (A transposed: [k][m])
#define CORE_8x8(SMA, SMB)                                                     \
    _Pragma("unroll")                                                          \
    for (int kk = 0; kk < 16; kk++) {                                          \
        float4 a0 = *(const float4*)&SMA[kk][ty << 2];                         \
        float4 a1 = *(const float4*)&SMA[kk][(ty << 2) + 64];                  \
        float4 b0 = *(const float4*)&SMB[kk][tx << 2];                         \
        float4 b1 = *(const float4*)&SMB[kk][(tx << 2) + 64];                  \
        u64 ap[4];                                                             \
        ap[0] = pack2(a0.x, a0.y); ap[1] = pack2(a0.z, a0.w);                  \
        ap[2] = pack2(a1.x, a1.y); ap[3] = pack2(a1.z, a1.w);                  \
        float bb_[8] = {b0.x, b0.y, b0.z, b0.w, b1.x, b1.y, b1.z, b1.w};       \
        _Pragma("unroll")                                                      \
        for (int j = 0; j < 8; j++) {                                          \
            u64 bj = pack2(bb_[j], bb_[j]);                                    \
            _Pragma("unroll")                                                  \
            for (int i = 0; i < 4; i++) FFMA2(acc[i][j], ap[i], bj);           \
        }                                                                      \
    }

// ---------------- 128x128 fp32 GEMM (NN): C = A[M,K]@B[K,N] + bias ---------
// optional per-row scale on A. grid: (N/128, M/128), 256 threads.
__global__ void __launch_bounds__(256) gemm128(
    const float* __restrict__ A, int lda,
    const float* __restrict__ B, int ldb,
    float* __restrict__ C, int ldc, int K,
    const float* __restrict__ bias,
    const float* __restrict__ rowscale)
{
    __shared__ float As[16][132];
    __shared__ float Bs[16][132];
    int tid = threadIdx.x;
    int tx = tid & 15, ty = tid >> 4;
    int m0 = blockIdx.y << 7, n0 = blockIdx.x << 7;

    int ar = tid >> 2, aq = (tid & 3) << 2;        // A loader: rows ar, ar+64; k-offset aq
    int bk = tid >> 4, bc = (tid & 15) << 2;       // B loader: k-row bk, cols bc, bc+64

    float rs0 = rowscale ? rowscale[m0 + ar]      : 1.0f;
    float rs1 = rowscale ? rowscale[m0 + ar + 64] : 1.0f;

    const float* Ap0 = A + (size_t)(m0 + ar) * lda + aq;
    const float* Ap1 = Ap0 + (size_t)64 * lda;
    const float* Bp  = B + (size_t)bk * ldb + n0 + bc;

    u64 acc[4][8];
#pragma unroll
    for (int i = 0; i < 4; i++)
#pragma unroll
        for (int j = 0; j < 8; j++) acc[i][j] = 0ull;

    float4 pa0 = *(const float4*)Ap0;
    float4 pa1 = *(const float4*)Ap1;
    float4 pb0 = *(const float4*)Bp;
    float4 pb1 = *(const float4*)(Bp + 64);

    for (int k0 = 0; k0 < K; k0 += 16) {
        As[aq + 0][ar]      = pa0.x * rs0;
        As[aq + 1][ar]      = pa0.y * rs0;
        As[aq + 2][ar]      = pa0.z * rs0;
        As[aq + 3][ar]      = pa0.w * rs0;
        As[aq + 0][ar + 64] = pa1.x * rs1;
        As[aq + 1][ar + 64] = pa1.y * rs1;
        As[aq + 2][ar + 64] = pa1.z * rs1;
        As[aq + 3][ar + 64] = pa1.w * rs1;
        *(float4*)&Bs[bk][bc]      = pb0;
        *(float4*)&Bs[bk][bc + 64] = pb1;
        __syncthreads();
        if (k0 + 16 < K) {
            pa0 = *(const float4*)(Ap0 + k0 + 16);
            pa1 = *(const float4*)(Ap1 + k0 + 16);
            pb0 = *(const float4*)(Bp + (size_t)(k0 + 16) * ldb);
            pb1 = *(const float4*)(Bp + (size_t)(k0 + 16) * ldb + 64);
        }
        CORE_8x8(As, Bs)
        __syncthreads();
    }

    float bv[8];
    if (bias) {
        float4 b4a = *(const float4*)&bias[n0 + (tx << 2)];
        float4 b4b = *(const float4*)&bias[n0 + (tx << 2) + 64];
        bv[0]=b4a.x; bv[1]=b4a.y; bv[2]=b4a.z; bv[3]=b4a.w;
        bv[4]=b4b.x; bv[5]=b4b.y; bv[6]=b4b.z; bv[7]=b4b.w;
    } else {
#pragma unroll
        for (int j = 0; j < 8; j++) bv[j] = 0.0f;
    }

#pragma unroll
    for (int i = 0; i < 4; i++) {
        int r = (i < 2) ? ((ty << 2) + (i << 1)) : (64 + (ty << 2) + ((i - 2) << 1));
        float* c0 = C + (size_t)(m0 + r) * ldc + n0;
        float* c1 = c0 + ldc;
        float4 o00, o01, o10, o11;
        float2 p;
        p = unpack2(acc[i][0]); o00.x = p.x + bv[0]; o10.x = p.y + bv[0];
        p = unpack2(acc[i][1]); o00.y = p.x + bv[1]; o10.y = p.y + bv[1];
        p = unpack2(acc[i][2]); o00.z = p.x + bv[2]; o10.z = p.y + bv[2];
        p = unpack2(acc[i][3]); o00.w = p.x + bv[3]; o10.w = p.y + bv[3];
        p = unpack2(acc[i][4]); o01.x = p.x + bv[4]; o11.x = p.y + bv[4];
        p = unpack2(acc[i][5]); o01.y = p.x + bv[5]; o11.y = p.y + bv[5];
        p = unpack2(acc[i][6]); o01.z = p.x + bv[6]; o11.z = p.y + bv[6];
        p = unpack2(acc[i][7]); o01.w = p.x + bv[7]; o11.w = p.y + bv[7];
        *(float4*)(c0 + (tx << 2))      = o00;
        *(float4*)(c0 + (tx << 2) + 64) = o01;
        *(float4*)(c1 + (tx << 2))      = o10;
        *(float4*)(c1 + (tx << 2) + 64) = o11;
    }
}

// ---------------- scores: S = QK^T/8 - 0.1*|q-k| + log(delta_k+1e-6) -------
// 128x128 tile, K=64. grid (L/128, L/128, B*H)
__global__ void __launch_bounds__(256) scores_kernel(
    const float* __restrict__ Q, const float* __restrict__ Kb,
    const float* __restrict__ delta, float* __restrict__ S)
{
    __shared__ float Qs[16][132];
    __shared__ float Ks[16][132];
    __shared__ float relb[128];
    int z = blockIdx.z, b = z >> 4, h = z & 15;
    int m0 = blockIdx.y << 7, n0 = blockIdx.x << 7;
    const float* Qb = Q  + (size_t)b * LL * DD + h * DK;
    const float* Kc = Kb + (size_t)b * LL * DD + h * DK;
    int tid = threadIdx.x, tx = tid & 15, ty = tid >> 4;
    int ar = tid >> 2, aq = (tid & 3) << 2;

    const float* Qp0 = Qb + (size_t)(m0 + ar) * DD + aq;
    const float* Qp1 = Qp0 + (size_t)64 * DD;
    const float* Kp0 = Kc + (size_t)(n0 + ar) * DD + aq;
    const float* Kp1 = Kp0 + (size_t)64 * DD;

    if (tid < 128) relb[tid] = logf(delta[(size_t)b * LL + n0 + tid] + 1e-6f);

    u64 acc[4][8];
#pragma unroll
    for (int i = 0; i < 4; i++)
#pragma unroll
        for (int j = 0; j < 8; j++) acc[i][j] = 0ull;

    float4 qa0 = *(const float4*)Qp0;
    float4 qa1 = *(const float4*)Qp1;
    float4 ka0 = *(const float4*)Kp0;
    float4 ka1 = *(const float4*)Kp1;

#pragma unroll
    for (int k0 = 0; k0 < DK; k0 += 16) {
        Qs[aq + 0][ar]      = qa0.x; Qs[aq + 1][ar]      = qa0.y;
        Qs[aq + 2][ar]      = qa0.z; Qs[aq + 3][ar]      = qa0.w;
        Qs[aq + 0][ar + 64] = qa1.x; Qs[aq + 1][ar + 64] = qa1.y;
        Qs[aq + 2][ar + 64] = qa1.z; Qs[aq + 3][ar + 64] = qa1.w;
        Ks[aq + 0][ar]      = ka0.x; Ks[aq + 1][ar]      = ka0.y;
        Ks[aq + 2][ar]      = ka0.z; Ks[aq + 3][ar]      = ka0.w;
        Ks[aq + 0][ar + 64] = ka1.x; Ks[aq + 1][ar + 64] = ka1.y;
        Ks[aq + 2][ar + 64] = ka1.z; Ks[aq + 3][ar + 64] = ka1.w;
        __syncthreads();
        if (k0 + 16 < DK) {
            qa0 = *(const float4*)(Qp0 + k0 + 16);
            qa1 = *(const float4*)(Qp1 + k0 + 16);
            ka0 = *(const float4*)(Kp0 + k0 + 16);
            ka1 = *(const float4*)(Kp1 + k0 + 16);
        }
        CORE_8x8(Qs, Ks)
        __syncthreads();
    }

    float relv[8];
#pragma unroll
    for (int j = 0; j < 4; j++) {
        relv[j]     = relb[(tx << 2) + j];
        relv[4 + j] = relb[64 + (tx << 2) + j];
    }

#pragma unroll
    for (int i = 0; i < 4; i++) {
        int r = (i < 2) ? ((ty << 2) + (i << 1)) : (64 + (ty << 2) + ((i - 2) << 1));
        int mlo = m0 + r, mhi = mlo + 1;
        float* s0 = S + ((size_t)z * LL + mlo) * LL + n0;
        float* s1 = s0 + LL;
        float4 o00, o01, o10, o11;
        float* po00 = (float*)&o00; float* po01 = (float*)&o01;
        float* po10 = (float*)&o10; float* po11 = (float*)&o11;
#pragma unroll
        for (int j = 0; j < 8; j++) {
            int ncol = (j < 4) ? ((tx << 2) + j) : (64 + (tx << 2) + (j - 4));
            int n = n0 + ncol;
            float2 p = unpack2(acc[i][j]);
            float v0 = p.x * 0.125f - 0.1f * fabsf((float)(mlo - n)) + relv[j];
            float v1 = p.y * 0.125f - 0.1f * fabsf((float)(mhi - n)) + relv[j];
            if (j < 4) { po00[j] = v0; po10[j] = v1; }
            else       { po01[j - 4] = v0; po11[j - 4] = v1; }
        }
        *(float4*)(s0 + (tx << 2))      = o00;
        *(float4*)(s0 + (tx << 2) + 64) = o01;
        *(float4*)(s1 + (tx << 2))      = o10;
        *(float4*)(s1 + (tx << 2) + 64) = o11;
    }
}

// ---------------- fused softmax (in place) + mean over heads ---------------
// one block per (b,q): 16 head-rows of 2048
__global__ void __launch_bounds__(256) softmax_mean_kernel(
    float* __restrict__ S, float* __restrict__ outm)
{
    int bq = blockIdx.x;
    int b = bq >> 11, q = bq & 2047;
    int tid = threadIdx.x;
    int wid = tid >> 5, lid = tid & 31;
    __shared__ float redm[8], reds[8];
    float macc[8];
#pragma unroll
    for (int j = 0; j < 8; j++) macc[j] = 0.0f;

    for (int h = 0; h < HH; h++) {
        float* row = S + (((size_t)(b * HH + h) * LL + q) * LL);
        float4 v0 = *(float4*)(row + (tid << 2));
        float4 v1 = *(float4*)(row + (tid << 2) + 1024);
        float p[8] = {v0.x, v0.y, v0.z, v0.w, v1.x, v1.y, v1.z, v1.w};

        float m = p[0];
#pragma unroll
        for (int j = 1; j < 8; j++) m = fmaxf(m, p[j]);
#pragma unroll
        for (int off = 16; off; off >>= 1) m = fmaxf(m, __shfl_xor_sync(0xffffffffu, m, off));
        if (lid == 0) redm[wid] = m;
        __syncthreads();
        m = redm[0];
#pragma unroll
        for (int w = 1; w < 8; w++) m = fmaxf(m, redm[w]);

        float s = 0.0f;
#pragma unroll
        for (int j = 0; j < 8; j++) { p[j] = fexp(p[j] - m); s += p[j]; }
#pragma unroll
        for (int off = 16; off; off >>= 1) s += __shfl_xor_sync(0xffffffffu, s, off);
        if (lid == 0) reds[wid] = s;
        __syncthreads();
        s = 0.0f;
#pragma unroll
        for (int w = 0; w < 8; w++) s += reds[w];

        float inv = 1.0f / s;
#pragma unroll
        for (int j = 0; j < 8; j++) { p[j] *= inv; macc[j] += p[j]; }
        v0.x = p[0]; v0.y = p[1]; v0.z = p[2]; v0.w = p[3];
        v1.x = p[4]; v1.y = p[5]; v1.z = p[6]; v1.w = p[7];
        *(float4*)(row + (tid << 2))        = v0;
        *(float4*)(row + (tid << 2) + 1024) = v1;
    }

    float* o = outm + ((size_t)bq * LL);
    float4 o0, o1;
    o0.x = macc[0] * 0.0625f; o0.y = macc[1] * 0.0625f;
    o0.z = macc[2] * 0.0625f; o0.w = macc[3] * 0.0625f;
    o1.x = macc[4] * 0.0625f; o1.y = macc[5] * 0.0625f;
    o1.z = macc[6] * 0.0625f; o1.w = macc[7] * 0.0625f;
    *(float4*)(o + (tid << 2))        = o0;
    *(float4*)(o + (tid << 2) + 1024) = o1;
}

// ---------------- context: ctx[b,:,h*64:+64] = P[b,h] @ V[b,h] -------------
// 128(M)x64(N) tile, 8x4 micro. grid (L/128, B*H)
__global__ void __launch_bounds__(256) context_gemm(
    const float* __restrict__ S, const float* __restrict__ V, float* __restrict__ ctx)
{
    __shared__ float As[16][132];
    __shared__ float Bs[16][68];
    int z = blockIdx.y, b = z >> 4, h = z & 15;
    int m0 = blockIdx.x << 7;
    const float* A  = S + (size_t)z * LL * LL;
    const float* Bv = V + (size_t)b * LL * DD + h * DK;
    int tid = threadIdx.x;
    int tx = tid & 15, ty = tid >> 4;
    int ar = tid >> 2, aq = (tid & 3) << 2;
    int bk = tid >> 4, bc = (tid & 15) << 2;

    const float* Ap0 = A + (size_t)(m0 + ar) * LL + aq;
    const float* Ap1 = Ap0 + (size_t)64 * LL;
    const float* Bp  = Bv + (size_t)bk * DD + bc;

    u64 acc[4][4];
#pragma unroll
    for (int i = 0; i < 4; i++)
#pragma unroll
        for (int j = 0; j < 4; j++) acc[i][j] = 0ull;

    float4 pa0 = *(const float4*)Ap0;
    float4 pa1 = *(const float4*)Ap1;
    float4 pb  = *(const float4*)Bp;

    for (int k0 = 0; k0 < LL; k0 += 16) {
        As[aq + 0][ar]      = pa0.x; As[aq + 1][ar]      = pa0.y;
        As[aq + 2][ar]      = pa0.z; As[aq + 3][ar]      = pa0.w;
        As[aq + 0][ar + 64] = pa1.x; As[aq + 1][ar + 64] = pa1.y;
        As[aq + 2][ar + 64] = pa1.z; As[aq + 3][ar + 64] = pa1.w;
        *(float4*)&Bs[bk][bc] = pb;
        __syncthreads();
        if (k0 + 16 < LL) {
            pa0 = *(const float4*)(Ap0 + k0 + 16);
            pa1 = *(const float4*)(Ap1 + k0 + 16);
            pb  = *(const float4*)(Bp + (size_t)(k0 + 16) * DD);
        }
#pragma unroll
        for (int kk = 0; kk < 16; kk++) {
            float4 a0 = *(const float4*)&As[kk][ty << 2];
            float4 a1 = *(const float4*)&As[kk][(ty << 2) + 64];
            float4 b4 = *(const float4*)&Bs[kk][tx << 2];
            u64 ap[4];
            ap[0] = pack2(a0.x, a0.y); ap[1] = pack2(a0.z, a0.w);
            ap[2] = pack2(a1.x, a1.y); ap[3] = pack2(a1.z, a1.w);
            float bb_[4] = {b4.x, b4.y, b4.z, b4.w};
#pragma unroll
            for (int j = 0; j < 4; j++) {
                u64 bj = pack2(bb_[j], bb_[j]);
#pragma unroll
                for (int i = 0; i < 4; i++) FFMA2(acc[i][j], ap[i], bj);
            }
        }
        __syncthreads();
    }

#pragma unroll
    for (int i = 0; i < 4; i++) {
        int r = (i < 2) ? ((ty << 2) + (i << 1)) : (64 + (ty << 2) + ((i - 2) << 1));
        float* c0 = ctx + ((size_t)b * LL + m0 + r) * DD + h * DK + (tx << 2);
        float* c1 = c0 + DD;
        float4 o0, o1;
        float2 p;
        p = unpack2(acc[i][0]); o0.x = p.x; o1.x = p.y;
        p = unpack2(acc[i][1]); o0.y = p.x; o1.y = p.y;
        p = unpack2(acc[i][2]); o0.z = p.x; o1.z = p.y;
        p = unpack2(acc[i][3]); o0.w = p.x; o1.w = p.y;
        *(float4*)c0 = o0;
        *(float4*)c1 = o1;
    }
}

// ---------------- launch ----------------------------------------------------
extern "C" void kernel_launch(void* const* d_in, const int* in_sizes, int n_in,
                              void* d_out, int out_size)
{
    const float* x   = (const float*)d_in[0];
    const float* dr  = (const float*)d_in[1];
    const float* Wq  = (const float*)d_in[2];
    const float* bq  = (const float*)d_in[3];
    const float* Wk  = (const float*)d_in[4];
    const float* bk  = (const float*)d_in[5];
    const float* Wv  = (const float*)d_in[6];
    const float* bv  = (const float*)d_in[7];
    const float* Wo  = (const float*)d_in[8];
    const float* bo  = (const float*)d_in[9];
    float* out = (float*)d_out;

    float *pQ, *pK, *pV, *pS, *pC;
    cudaGetSymbolAddress((void**)&pQ, g_Q);
    cudaGetSymbolAddress((void**)&pK, g_K);
    cudaGetSymbolAddress((void**)&pV, g_V);
    cudaGetSymbolAddress((void**)&pS, g_S);
    cudaGetSymbolAddress((void**)&pC, g_ctx);

    dim3 gproj(DD / 128, BL / 128);            // (8, 32)
    gemm128<<<gproj, 256>>>(x, DD, Wq, DD, pQ, DD, DD, bq, nullptr);
    gemm128<<<gproj, 256>>>(x, DD, Wk, DD, pK, DD, DD, bk, nullptr);
    gemm128<<<gproj, 256>>>(x, DD, Wv, DD, pV, DD, DD, bv, dr);

    dim3 gsc(LL / 128, LL / 128, BB * HH);     // (16, 16, 32)
    scores_kernel<<<gsc, 256>>>(pQ, pK, dr, pS);

    if (out_size >= (BL * DD + BB * LL * LL)) {
        softmax_mean_kernel<<<BB * LL, 256>>>(pS, out + (size_t)BL * DD);
    }

    dim3 gctx(LL / 128, BB * HH);              // (16, 32)
    context_gemm<<<gctx, 256>>>(pS, pV, pC);

    gemm128<<<gproj, 256>>>(pC, DD, Wo, DD, out, DD, DD, bo, nullptr);
}